// round 2
// baseline (speedup 1.0000x reference)
#include <cuda_runtime.h>

#define DD     262144     // 512*512
#define NB     128        // batch
#define NENV   4
#define KSEL   26214      // floor(0.1 * 512 * 512)
#define NBIN   65536

// Scratch (allocation-free: __device__ globals)
__device__ float    g_M[NENV][DD];        // per-env logits matrices (4 MB)
__device__ unsigned g_hist[NENV][NBIN];   // radix pass 1 (hi 16 bits)
__device__ unsigned g_hist2[NENV][NBIN];  // radix pass 2 (lo 16 bits)
__device__ unsigned g_binhi[NENV];
__device__ unsigned g_rank[NENV];
__device__ unsigned g_kth[NENV];          // exact key of k-th largest per env

// Monotone mapping: float total order -> unsigned total order
__device__ __forceinline__ unsigned fkey(float f) {
    unsigned u = __float_as_uint(f);
    return (u & 0x80000000u) ? ~u : (u | 0x80000000u);
}
__device__ __forceinline__ float sigm(float x) {
    return 1.0f / (1.0f + __expf(-x));
}

__global__ void k_zero() {
    int stride = gridDim.x * blockDim.x;
    unsigned* h1 = &g_hist[0][0];
    unsigned* h2 = &g_hist2[0][0];
    for (int j = blockIdx.x * blockDim.x + threadIdx.x; j < NENV * NBIN; j += stride) {
        h1[j] = 0u;
        h2[j] = 0u;
    }
}

// Build per-env matrices + hi-16 histogram
__global__ void k_build(const float* __restrict__ base, const float* __restrict__ deltas) {
    int e = blockIdx.y;
    int i = (blockIdx.x * blockDim.x + threadIdx.x) * 4;
    float4 b4 = *(const float4*)(base + i);
    float4 d4 = *(const float4*)(deltas + (size_t)e * DD + i);
    float4 m;
    m.x = b4.x + d4.x; m.y = b4.y + d4.y;
    m.z = b4.z + d4.z; m.w = b4.w + d4.w;
    *(float4*)(&g_M[e][i]) = m;
    atomicAdd(&g_hist[e][fkey(m.x) >> 16], 1u);
    atomicAdd(&g_hist[e][fkey(m.y) >> 16], 1u);
    atomicAdd(&g_hist[e][fkey(m.z) >> 16], 1u);
    atomicAdd(&g_hist[e][fkey(m.w) >> 16], 1u);
}

// Descending scan of a 65536-bin histogram to locate the bin holding rank `target`.
// phase 0: hist -> (binhi, remaining rank); phase 1: hist2 -> final kth key.
__global__ void k_scan(int phase) {
    int e = blockIdx.x;
    const unsigned* h = (phase == 0) ? &g_hist[e][0] : &g_hist2[e][0];
    __shared__ unsigned csum[1024];
    int t = threadIdx.x;
    unsigned s = 0;
    for (int j = 0; j < 64; j++) s += h[t * 64 + j];
    csum[t] = s;
    __syncthreads();
    if (t == 0) {
        unsigned target = (phase == 0) ? (unsigned)KSEL : g_rank[e];
        unsigned cum = 0;
        int c = 1023;
        for (; c > 0; c--) {
            if (cum + csum[c] >= target) break;
            cum += csum[c];
        }
        unsigned bin = (unsigned)(c * 64);
        for (int j = 63; j >= 0; j--) {
            unsigned v = h[c * 64 + j];
            if (cum + v >= target) { bin = (unsigned)(c * 64 + j); break; }
            cum += v;
        }
        if (phase == 0) {
            g_binhi[e] = bin;
            g_rank[e]  = target - cum;   // rank within the hi-bin (>=1)
        } else {
            g_kth[e] = (g_binhi[e] << 16) | bin;
        }
    }
}

// Lo-16 histogram restricted to the selected hi-bin
__global__ void k_hist2() {
    int e = blockIdx.y;
    int i = (blockIdx.x * blockDim.x + threadIdx.x) * 4;
    unsigned hi = g_binhi[e];
    float4 m = *(const float4*)(&g_M[e][i]);
    unsigned k0 = fkey(m.x), k1 = fkey(m.y), k2 = fkey(m.z), k3 = fkey(m.w);
    if ((k0 >> 16) == hi) atomicAdd(&g_hist2[e][k0 & 0xFFFFu], 1u);
    if ((k1 >> 16) == hi) atomicAdd(&g_hist2[e][k1 & 0xFFFFu], 1u);
    if ((k2 >> 16) == hi) atomicAdd(&g_hist2[e][k2 & 0xFFFFu], 1u);
    if ((k3 >> 16) == hi) atomicAdd(&g_hist2[e][k3 & 0xFFFFu], 1u);
}

// Streaming epilogue: 3 coalesced float4 store streams per batch row.
__global__ void k_out(const int* __restrict__ env_idx,
                      float* __restrict__ outA,
                      float* __restrict__ outL,
                      float* __restrict__ outS) {
    int b = blockIdx.y;
    int e = env_idx[b];
    unsigned kth = g_kth[e];
    size_t i = ((size_t)blockIdx.x * blockDim.x + threadIdx.x) * 4;
    float4 m = *(const float4*)(&g_M[e][i]);
    float4 s;
    s.x = sigm(m.x); s.y = sigm(m.y); s.z = sigm(m.z); s.w = sigm(m.w);
    float4 a;
    a.x = (fkey(m.x) >= kth) ? s.x : 0.0f;
    a.y = (fkey(m.y) >= kth) ? s.y : 0.0f;
    a.z = (fkey(m.z) >= kth) ? s.z : 0.0f;
    a.w = (fkey(m.w) >= kth) ? s.w : 0.0f;
    size_t off = (size_t)b * DD + i;
    *(float4*)(outA + off) = a;
    *(float4*)(outL + off) = m;
    *(float4*)(outS + off) = s;
}

extern "C" void kernel_launch(void* const* d_in, const int* in_sizes, int n_in,
                              void* d_out, int out_size) {
    const float* base   = nullptr;
    const float* deltas = nullptr;
    const int*   env    = nullptr;
    for (int i = 0; i < n_in; i++) {
        if      (in_sizes[i] == DD)        base   = (const float*)d_in[i];
        else if (in_sizes[i] == NENV * DD) deltas = (const float*)d_in[i];
        else if (in_sizes[i] == NB)        env    = (const int*)d_in[i];
        // z_s (131072 elems) is unused by the reference outputs
    }

    k_zero<<<64, 256>>>();

    dim3 gb(DD / (256 * 4), NENV);      // (256, 4)
    k_build<<<gb, 256>>>(base, deltas);
    k_scan<<<NENV, 1024>>>(0);
    k_hist2<<<gb, 256>>>();
    k_scan<<<NENV, 1024>>>(1);

    float* outA = (float*)d_out;                 // tuple order: (A, A_logits, A_soft)
    float* outL = outA + (size_t)NB * DD;
    float* outS = outL + (size_t)NB * DD;
    dim3 go(DD / (256 * 4), NB);                 // (256, 128)
    k_out<<<go, 256>>>(env, outA, outL, outS);
}